// round 5
// baseline (speedup 1.0000x reference)
#include <cuda_runtime.h>
#include <math.h>

#define DIM    256
#define LINE   24
#define HEADS  8
#define DHEAD  64
#define INNER  512
#define NROWS  196608
#define NBLK   (NROWS / LINE)   // 8192

// ---------------------------------------------------------------------------
// Scratch (device globals: allocation-free, BSS zero-init)
// ---------------------------------------------------------------------------
__device__ float g_q[(size_t)NROWS * INNER];        // 402 MB
__device__ float g_kv[(size_t)NROWS * 2 * INNER];   // 805 MB
__device__ float g_inner[(size_t)NROWS * INNER];    // 402 MB

// ---------------------------------------------------------------------------
// TF32 helpers
// ---------------------------------------------------------------------------
__device__ __forceinline__ float f2tf32(float f) {
    unsigned r;
    asm("cvt.rna.tf32.f32 %0, %1;" : "=r"(r) : "f"(f));
    return __uint_as_float(r);
}

// ---------------------------------------------------------------------------
// GEMM: C[M,N] = A[M,K] @ B[K,N] (+ bias), tf32 mma.sync, fp32 accumulate
// A,B,C row-major. Requires M%128==0, N%128==0, K%32==0 (true for all calls).
// ---------------------------------------------------------------------------
#define BM 128
#define BN 128
#define BK 32
#define ASTR (BK + 4)   // 36 floats  -> conflict-free fragment reads
#define BSTR (BN + 4)   // 132 floats

__global__ void __launch_bounds__(256) gemm_tf32_kernel(
    const float* __restrict__ A, const float* __restrict__ B,
    const float* __restrict__ bias, float* __restrict__ C,
    int M, int N, int K)
{
    __shared__ float As[BM * ASTR];
    __shared__ float Bs[BK * BSTR];

    const int tid  = threadIdx.x;
    const int wid  = tid >> 5;
    const int lane = tid & 31;
    const int g    = lane >> 2;   // 0..7  (group id)
    const int tg   = lane & 3;    // 0..3  (thread-in-group)

    const int mBase = blockIdx.y * BM;
    const int nBase = blockIdx.x * BN;
    // 8 warps: 2 (M) x 4 (N); warp tile 64x32
    const int wm = (wid >> 2) * 64;
    const int wn = (wid & 3) * 32;

    float acc[4][4][4];
    #pragma unroll
    for (int a = 0; a < 4; a++)
        #pragma unroll
        for (int b = 0; b < 4; b++)
            #pragma unroll
            for (int c = 0; c < 4; c++) acc[a][b][c] = 0.f;

    for (int k0 = 0; k0 < K; k0 += BK) {
        // ---- stage A tile [BM x BK], coalesced float4 along K, convert to tf32
        #pragma unroll
        for (int i = 0; i < 4; i++) {
            int idx = tid + i * 256;            // 0..1023
            int r = idx >> 3, cq = idx & 7;
            float4 v = *(const float4*)(A + (size_t)(mBase + r) * K + k0 + cq * 4);
            float* d = As + r * ASTR + cq * 4;
            d[0] = f2tf32(v.x); d[1] = f2tf32(v.y);
            d[2] = f2tf32(v.z); d[3] = f2tf32(v.w);
        }
        // ---- stage B tile [BK x BN], coalesced float4 along N
        #pragma unroll
        for (int i = 0; i < 4; i++) {
            int idx = tid + i * 256;
            int r = idx >> 5, nq = idx & 31;
            float4 v = *(const float4*)(B + (size_t)(k0 + r) * N + nBase + nq * 4);
            float* d = Bs + r * BSTR + nq * 4;
            d[0] = f2tf32(v.x); d[1] = f2tf32(v.y);
            d[2] = f2tf32(v.z); d[3] = f2tf32(v.w);
        }
        __syncthreads();

        #pragma unroll
        for (int kk = 0; kk < BK; kk += 8) {
            unsigned af[4][4];
            #pragma unroll
            for (int mi = 0; mi < 4; mi++) {
                const float* ap = As + (wm + mi * 16) * ASTR + kk;
                af[mi][0] = __float_as_uint(ap[g * ASTR + tg]);
                af[mi][1] = __float_as_uint(ap[(g + 8) * ASTR + tg]);
                af[mi][2] = __float_as_uint(ap[g * ASTR + tg + 4]);
                af[mi][3] = __float_as_uint(ap[(g + 8) * ASTR + tg + 4]);
            }
            unsigned bf[4][2];
            #pragma unroll
            for (int ni = 0; ni < 4; ni++) {
                const float* bp = Bs + kk * BSTR + wn + ni * 8;
                bf[ni][0] = __float_as_uint(bp[tg * BSTR + g]);
                bf[ni][1] = __float_as_uint(bp[(tg + 4) * BSTR + g]);
            }
            #pragma unroll
            for (int mi = 0; mi < 4; mi++)
                #pragma unroll
                for (int ni = 0; ni < 4; ni++) {
                    asm volatile(
                        "mma.sync.aligned.m16n8k8.row.col.f32.tf32.tf32.f32 "
                        "{%0,%1,%2,%3},{%4,%5,%6,%7},{%8,%9},{%0,%1,%2,%3};"
                        : "+f"(acc[mi][ni][0]), "+f"(acc[mi][ni][1]),
                          "+f"(acc[mi][ni][2]), "+f"(acc[mi][ni][3])
                        : "r"(af[mi][0]), "r"(af[mi][1]),
                          "r"(af[mi][2]), "r"(af[mi][3]),
                          "r"(bf[ni][0]), "r"(bf[ni][1]));
                }
        }
        __syncthreads();
    }

    // ---- epilogue
    #pragma unroll
    for (int mi = 0; mi < 4; mi++) {
        int r0 = mBase + wm + mi * 16 + g;
        #pragma unroll
        for (int ni = 0; ni < 4; ni++) {
            int c0 = nBase + wn + ni * 8 + tg * 2;
            float b0 = 0.f, b1 = 0.f;
            if (bias) { b0 = bias[c0]; b1 = bias[c0 + 1]; }
            C[(size_t)r0 * N + c0]           = acc[mi][ni][0] + b0;
            C[(size_t)r0 * N + c0 + 1]       = acc[mi][ni][1] + b1;
            C[(size_t)(r0 + 8) * N + c0]     = acc[mi][ni][2] + b0;
            C[(size_t)(r0 + 8) * N + c0 + 1] = acc[mi][ni][3] + b1;
        }
    }
}

// ---------------------------------------------------------------------------
// Attention: one CTA per line-block (24 rows), one warp per head. Pure fp32.
// q layout: [N, 512]; kv layout: [N, 1024] (k = cols [0,512), v = [512,1024))
// ---------------------------------------------------------------------------
#define QSTR 65                              // padded row stride (bank spread)
#define HEAD_SM (3 * LINE * QSTR)            // per-warp q/k/v region (floats)
#define SIM_STR 25
#define ATTN_SMEM_BYTES ((HEADS * HEAD_SM + HEADS * LINE * SIM_STR) * 4)

__global__ void __launch_bounds__(256) attn_kernel(
    const float* __restrict__ q, const float* __restrict__ kv,
    const float* __restrict__ pos, float* __restrict__ inner)
{
    extern __shared__ float sm[];
    const int b    = blockIdx.x;
    const int w    = threadIdx.x >> 5;   // head
    const int lane = threadIdx.x & 31;

    float* qs   = sm + w * HEAD_SM;
    float* ks   = qs + LINE * QSTR;
    float* vs   = ks + LINE * QSTR;
    float* sims = sm + HEADS * HEAD_SM + w * (LINE * SIM_STR);

    const float* qg = q  + (size_t)b * LINE * INNER     + w * DHEAD;
    const float* kg = kv + (size_t)b * LINE * 2 * INNER + w * DHEAD;
    const float* vg = kg + INNER;

    for (int t = lane; t < LINE * DHEAD; t += 32) {
        int i = t >> 6, d = t & 63;
        qs[i * QSTR + d] = qg[(size_t)i * INNER + d];
        ks[i * QSTR + d] = kg[(size_t)i * 2 * INNER + d];
        vs[i * QSTR + d] = vg[(size_t)i * 2 * INNER + d];
    }
    __syncwarp();

    const float scale = 0.125f;              // 64^-0.5
    const float* pe = pos + w * LINE * LINE;
    for (int e = lane; e < LINE * LINE; e += 32) {
        int i = e / LINE, j = e - i * LINE;
        float s = 0.f;
        #pragma unroll
        for (int d = 0; d < DHEAD; d++)
            s += qs[i * QSTR + d] * ks[j * QSTR + d];
        sims[i * SIM_STR + j] = s * scale + pe[e];
    }
    __syncwarp();

    if (lane < LINE) {
        float m = -1e30f;
        #pragma unroll
        for (int j = 0; j < LINE; j++) m = fmaxf(m, sims[lane * SIM_STR + j]);
        float ssum = 0.f;
        #pragma unroll
        for (int j = 0; j < LINE; j++) {
            float p = __expf(sims[lane * SIM_STR + j] - m);
            sims[lane * SIM_STR + j] = p;
            ssum += p;
        }
        float inv = 1.f / ssum;
        #pragma unroll
        for (int j = 0; j < LINE; j++) sims[lane * SIM_STR + j] *= inv;
    }
    __syncwarp();

    float* og = inner + (size_t)b * LINE * INNER + w * DHEAD;
    for (int i = 0; i < LINE; i++) {
        #pragma unroll
        for (int dd = 0; dd < 2; dd++) {
            int d = lane + dd * 32;
            float s = 0.f;
            #pragma unroll
            for (int j = 0; j < LINE; j++)
                s += sims[i * SIM_STR + j] * vs[j * QSTR + d];
            og[(size_t)i * INNER + d] = s;
        }
    }
}

// ---------------------------------------------------------------------------
// Launch
// ---------------------------------------------------------------------------
extern "C" void kernel_launch(void* const* d_in, const int* in_sizes, int n_in,
                              void* d_out, int out_size)
{
    (void)in_sizes; (void)n_in; (void)out_size;
    const float* x    = (const float*)d_in[0];
    const float* Wq   = (const float*)d_in[1];
    const float* Wkv  = (const float*)d_in[2];
    const float* Wout = (const float*)d_in[3];
    const float* bout = (const float*)d_in[4];
    const float* pos  = (const float*)d_in[5];
    float* out = (float*)d_out;

    float *qb, *kvb, *ib;
    cudaGetSymbolAddress((void**)&qb,  g_q);
    cudaGetSymbolAddress((void**)&kvb, g_kv);
    cudaGetSymbolAddress((void**)&ib,  g_inner);

    cudaFuncSetAttribute(attn_kernel,
                         cudaFuncAttributeMaxDynamicSharedMemorySize,
                         ATTN_SMEM_BYTES);

    // 1) q = x @ Wq                    [196608,256] @ [256,512]
    dim3 gq(INNER / BN, NROWS / BM);
    gemm_tf32_kernel<<<gq, 256>>>(x, Wq, nullptr, qb, NROWS, INNER, DIM);

    // 2) kv = x @ Wkv                  [196608,256] @ [256,1024]
    dim3 gkv(2 * INNER / BN, NROWS / BM);
    gemm_tf32_kernel<<<gkv, 256>>>(x, Wkv, nullptr, kvb, NROWS, 2 * INNER, DIM);

    // 3) attention per line-block
    attn_kernel<<<NBLK, 256, ATTN_SMEM_BYTES>>>(qb, kvb, pos, ib);

    // 4) out = inner @ Wout + b_out    [196608,512] @ [512,256]
    dim3 go(DIM / BN, NROWS / BM);
    gemm_tf32_kernel<<<go, 256>>>(ib, Wout, bout, out, NROWS, DIM, INNER);
}

// round 6
// speedup vs baseline: 2.1906x; 2.1906x over previous
#include <cuda_runtime.h>
#include <cuda_fp16.h>
#include <math.h>

#define DIM    256
#define LINE   24
#define HEADS  8
#define DHEAD  64
#define INNER  512
#define NROWS  196608
#define NBLK   (NROWS / LINE)   // 8192

// ---------------------------------------------------------------------------
// Scratch (device globals, allocation-free)
// ---------------------------------------------------------------------------
__device__ __half g_xh  [(size_t)NROWS * DIM];        // 100 MB
__device__ __half g_wqh [DIM * INNER];
__device__ __half g_wkvh[DIM * 2 * INNER];
__device__ __half g_wouth[INNER * DIM];
__device__ __half g_qh  [(size_t)NROWS * INNER];      // 201 MB
__device__ __half g_kvh [(size_t)NROWS * 2 * INNER];  // 403 MB
__device__ __half g_ih  [(size_t)NROWS * INNER];      // 201 MB

// ---------------------------------------------------------------------------
// fp32 -> fp16 conversion (vectorized)
// ---------------------------------------------------------------------------
__global__ void __launch_bounds__(256) f2h_kernel(
    const float* __restrict__ in, __half* __restrict__ out, int n)
{
    int i = (blockIdx.x * blockDim.x + threadIdx.x) * 4;
    if (i < n) {
        float4 v = *(const float4*)(in + i);
        __half2 a = __floats2half2_rn(v.x, v.y);
        __half2 b = __floats2half2_rn(v.z, v.w);
        *(__half2*)(out + i)     = a;
        *(__half2*)(out + i + 2) = b;
    }
}

// ---------------------------------------------------------------------------
// fp16 GEMM: C[M,N] = A[M,K] @ B[K,N] (+bias), m16n8k16 HMMA, fp32 accum,
// ldmatrix fragments, cp.async double buffering.
// M%128==0, N%128==0, K%64==0 (all calls satisfy).
// ---------------------------------------------------------------------------
#define GBM 128
#define GBN 128
#define GBK 64
#define AS  72    // half stride (144 B)  -> bank step 4 mod 32, LDSM conflict-free
#define BS  136   // half stride (272 B)  -> bank step 4 mod 32
#define GEMM_SMEM ((2*GBM*AS + 2*GBK*BS) * 2)   // 71680 bytes

template<bool HALF_OUT>
__global__ void __launch_bounds__(256) gemm_f16(
    const __half* __restrict__ A, const __half* __restrict__ B,
    const float* __restrict__ bias, void* __restrict__ Cout,
    int M, int N, int K)
{
    extern __shared__ __half sh[];
    __half* As = sh;
    __half* Bs = sh + 2 * GBM * AS;

    const int tid  = threadIdx.x;
    const int lane = tid & 31;
    const int wid  = tid >> 5;
    const int g    = lane >> 2;
    const int tg   = lane & 3;
    const int mBase = blockIdx.y * GBM;
    const int nBase = blockIdx.x * GBN;
    const int wm = (wid >> 2) * 64;   // 8 warps: 2(M) x 4(N), warp tile 64x32
    const int wn = (wid & 3) * 32;

    float acc[4][4][4];
    #pragma unroll
    for (int a = 0; a < 4; a++)
        #pragma unroll
        for (int b = 0; b < 4; b++)
            #pragma unroll
            for (int c = 0; c < 4; c++) acc[a][b][c] = 0.f;

    // ldmatrix lane addressing
    const int aRow = (lane & 7) + ((lane >> 3) & 1) * 8;   // + wm + mi*16
    const int aKo  = ((lane >> 4) & 1) * 8;
    const int bKr  = (lane & 7) + ((lane >> 3) & 1) * 8;
    const int bNc  = wn + ((lane >> 4) & 1) * 8;           // + nb*16

    auto stage = [&](int k0, int buf) {
        __half* Ad = As + buf * GBM * AS;
        __half* Bd = Bs + buf * GBK * BS;
        #pragma unroll
        for (int i = 0; i < 4; i++) {           // A: 128 rows x 8 chunks(16B)
            int id = tid + i * 256;
            int r = id >> 3, c = id & 7;
            const __half* src = A + (size_t)(mBase + r) * K + k0 + c * 8;
            unsigned dst = (unsigned)__cvta_generic_to_shared(Ad + r * AS + c * 8);
            asm volatile("cp.async.cg.shared.global [%0], [%1], 16;\n"
                         :: "r"(dst), "l"(src));
        }
        #pragma unroll
        for (int i = 0; i < 4; i++) {           // B: 64 rows x 16 chunks
            int id = tid + i * 256;
            int r = id >> 4, c = id & 15;
            const __half* src = B + (size_t)(k0 + r) * N + nBase + c * 8;
            unsigned dst = (unsigned)__cvta_generic_to_shared(Bd + r * BS + c * 8);
            asm volatile("cp.async.cg.shared.global [%0], [%1], 16;\n"
                         :: "r"(dst), "l"(src));
        }
    };

    const int KT = K / GBK;
    stage(0, 0);
    asm volatile("cp.async.commit_group;\n" ::: "memory");

    for (int kt = 0; kt < KT; kt++) {
        if (kt + 1 < KT) {
            stage((kt + 1) * GBK, (kt + 1) & 1);
            asm volatile("cp.async.commit_group;\n" ::: "memory");
            asm volatile("cp.async.wait_group 1;\n" ::: "memory");
        } else {
            asm volatile("cp.async.wait_group 0;\n" ::: "memory");
        }
        __syncthreads();

        const __half* Ab = As + (kt & 1) * GBM * AS;
        const __half* Bb = Bs + (kt & 1) * GBK * BS;

        #pragma unroll
        for (int kk = 0; kk < GBK; kk += 16) {
            unsigned a[4][4], b[2][4];
            #pragma unroll
            for (int mi = 0; mi < 4; mi++) {
                unsigned sa = (unsigned)__cvta_generic_to_shared(
                    Ab + (wm + mi * 16 + aRow) * AS + kk + aKo);
                asm volatile(
                    "ldmatrix.sync.aligned.m8n8.x4.shared.b16 {%0,%1,%2,%3},[%4];\n"
                    : "=r"(a[mi][0]), "=r"(a[mi][1]), "=r"(a[mi][2]), "=r"(a[mi][3])
                    : "r"(sa));
            }
            #pragma unroll
            for (int nb = 0; nb < 2; nb++) {
                unsigned sb = (unsigned)__cvta_generic_to_shared(
                    Bb + (kk + bKr) * BS + bNc + nb * 16);
                asm volatile(
                    "ldmatrix.sync.aligned.m8n8.x4.trans.shared.b16 {%0,%1,%2,%3},[%4];\n"
                    : "=r"(b[nb][0]), "=r"(b[nb][1]), "=r"(b[nb][2]), "=r"(b[nb][3])
                    : "r"(sb));
            }
            #pragma unroll
            for (int mi = 0; mi < 4; mi++)
                #pragma unroll
                for (int ni = 0; ni < 4; ni++) {
                    asm volatile(
                        "mma.sync.aligned.m16n8k16.row.col.f32.f16.f16.f32 "
                        "{%0,%1,%2,%3},{%4,%5,%6,%7},{%8,%9},{%0,%1,%2,%3};\n"
                        : "+f"(acc[mi][ni][0]), "+f"(acc[mi][ni][1]),
                          "+f"(acc[mi][ni][2]), "+f"(acc[mi][ni][3])
                        : "r"(a[mi][0]), "r"(a[mi][1]), "r"(a[mi][2]), "r"(a[mi][3]),
                          "r"(b[ni >> 1][(ni & 1) * 2]),
                          "r"(b[ni >> 1][(ni & 1) * 2 + 1]));
                }
        }
        __syncthreads();
    }

    // epilogue
    #pragma unroll
    for (int mi = 0; mi < 4; mi++) {
        int r0 = mBase + wm + mi * 16 + g;
        #pragma unroll
        for (int ni = 0; ni < 4; ni++) {
            int c0 = nBase + wn + ni * 8 + 2 * tg;
            if (HALF_OUT) {
                __half* C = (__half*)Cout;
                *(__half2*)(C + (size_t)r0 * N + c0) =
                    __floats2half2_rn(acc[mi][ni][0], acc[mi][ni][1]);
                *(__half2*)(C + (size_t)(r0 + 8) * N + c0) =
                    __floats2half2_rn(acc[mi][ni][2], acc[mi][ni][3]);
            } else {
                float* C = (float*)Cout;
                float b0 = bias ? bias[c0] : 0.f;
                float b1 = bias ? bias[c0 + 1] : 0.f;
                C[(size_t)r0 * N + c0]           = acc[mi][ni][0] + b0;
                C[(size_t)r0 * N + c0 + 1]       = acc[mi][ni][1] + b1;
                C[(size_t)(r0 + 8) * N + c0]     = acc[mi][ni][2] + b0;
                C[(size_t)(r0 + 8) * N + c0 + 1] = acc[mi][ni][3] + b1;
            }
        }
    }
}

// ---------------------------------------------------------------------------
// f32x2 packed math helpers (sm_103a FFMA2)
// ---------------------------------------------------------------------------
__device__ __forceinline__ unsigned long long pk2(float a, float b) {
    unsigned long long r;
    asm("mov.b64 %0,{%1,%2};" : "=l"(r) : "f"(a), "f"(b));
    return r;
}
__device__ __forceinline__ unsigned long long fma2(
    unsigned long long a, unsigned long long b, unsigned long long c) {
    unsigned long long d;
    asm("fma.rn.f32x2 %0,%1,%2,%3;" : "=l"(d) : "l"(a), "l"(b), "l"(c));
    return d;
}
__device__ __forceinline__ float2 upk2(unsigned long long a) {
    float2 f;
    asm("mov.b64 {%0,%1},%2;" : "=f"(f.x), "=f"(f.y) : "l"(a));
    return f;
}

// ---------------------------------------------------------------------------
// Attention: CTA = one line-block, warp = one head.
// q rows register-resident, k/v fp32 in smem read via broadcast LDS.128,
// all FMAs packed f32x2, softmax in registers, fp16 I/O.
// ---------------------------------------------------------------------------
#define ATTN_SMEM (HEADS * 2 * LINE * DHEAD * 4)   // 98304 bytes

__global__ void __launch_bounds__(256, 2) attn_f16(
    const __half* __restrict__ q, const __half* __restrict__ kv,
    const float* __restrict__ pos, __half* __restrict__ inner)
{
    extern __shared__ float sm[];
    const int b    = blockIdx.x;
    const int w    = threadIdx.x >> 5;
    const int lane = threadIdx.x & 31;

    float* ks = sm + w * (2 * LINE * DHEAD);
    float* vs = ks + LINE * DHEAD;

    // ---- stage k, v (fp16 -> fp32), coalesced 128B per iteration
    const __half2* kv2 = (const __half2*)kv;
    size_t kbase = (size_t)b * LINE * 512 + (size_t)w * 32;   // half2 units
    #pragma unroll
    for (int t = lane; t < LINE * 32; t += 32) {
        int i = t >> 5, d2 = t & 31;
        float2 kf = __half22float2(kv2[kbase + (size_t)i * 512 + d2]);
        *(float2*)&ks[i * DHEAD + d2 * 2] = kf;
        float2 vf = __half22float2(kv2[kbase + (size_t)i * 512 + 256 + d2]);
        *(float2*)&vs[i * DHEAD + d2 * 2] = vf;
    }
    __syncwarp();

    if (lane < LINE) {
        // ---- q row into packed registers
        unsigned long long qp[32];
        const uint4* q4 = (const uint4*)(q + (size_t)(b * LINE + lane) * INNER
                                           + w * DHEAD);
        #pragma unroll
        for (int c = 0; c < 8; c++) {
            uint4 u = q4[c];
            const __half2* hp = (const __half2*)&u;
            #pragma unroll
            for (int h = 0; h < 4; h++) {
                float2 f = __half22float2(hp[h]);
                qp[c * 4 + h] = pk2(f.x, f.y);
            }
        }

        // ---- sims (broadcast LDS.128 of k rows)
        float p[LINE];
        #pragma unroll
        for (int j = 0; j < LINE; j++) {
            const ulonglong2* kr = (const ulonglong2*)(ks + j * DHEAD);
            unsigned long long s0 = 0, s1 = 0, s2 = 0, s3 = 0;
            #pragma unroll
            for (int c = 0; c < 8; c++) {
                ulonglong2 k0 = kr[2 * c], k1 = kr[2 * c + 1];
                s0 = fma2(qp[4 * c + 0], k0.x, s0);
                s1 = fma2(qp[4 * c + 1], k0.y, s1);
                s2 = fma2(qp[4 * c + 2], k1.x, s2);
                s3 = fma2(qp[4 * c + 3], k1.y, s3);
            }
            float2 f0 = upk2(s0), f1 = upk2(s1), f2 = upk2(s2), f3 = upk2(s3);
            p[j] = ((f0.x + f0.y) + (f1.x + f1.y)) +
                   ((f2.x + f2.y) + (f3.x + f3.y));
        }

        // ---- + pos_emb, softmax (registers)
        const float4* pe4 = (const float4*)(pos + (size_t)w * LINE * LINE
                                              + lane * LINE);
        #pragma unroll
        for (int c = 0; c < 6; c++) {
            float4 pe = pe4[c];
            p[4 * c + 0] = p[4 * c + 0] * 0.125f + pe.x;
            p[4 * c + 1] = p[4 * c + 1] * 0.125f + pe.y;
            p[4 * c + 2] = p[4 * c + 2] * 0.125f + pe.z;
            p[4 * c + 3] = p[4 * c + 3] * 0.125f + pe.w;
        }
        float m = -1e30f;
        #pragma unroll
        for (int j = 0; j < LINE; j++) m = fmaxf(m, p[j]);
        float ssum = 0.f;
        #pragma unroll
        for (int j = 0; j < LINE; j++) { p[j] = __expf(p[j] - m); ssum += p[j]; }
        float inv = 1.f / ssum;
        #pragma unroll
        for (int j = 0; j < LINE; j++) p[j] *= inv;

        // ---- out = P @ V, two 32-wide halves (32 packed accumulators each)
        __half* og = inner + (size_t)(b * LINE + lane) * INNER + w * DHEAD;
        #pragma unroll
        for (int h2 = 0; h2 < 2; h2++) {
            unsigned long long a[16];
            #pragma unroll
            for (int c = 0; c < 16; c++) a[c] = 0;
            #pragma unroll
            for (int j = 0; j < LINE; j++) {
                unsigned long long pj = pk2(p[j], p[j]);
                const ulonglong2* vr =
                    (const ulonglong2*)(vs + j * DHEAD + h2 * 32);
                #pragma unroll
                for (int c = 0; c < 8; c++) {
                    ulonglong2 vv = vr[c];
                    a[2 * c]     = fma2(pj, vv.x, a[2 * c]);
                    a[2 * c + 1] = fma2(pj, vv.y, a[2 * c + 1]);
                }
            }
            unsigned oh[16];
            #pragma unroll
            for (int c = 0; c < 16; c++) {
                float2 f = upk2(a[c]);
                __half2 h = __floats2half2_rn(f.x, f.y);
                oh[c] = *(unsigned*)&h;
            }
            uint4* o4 = (uint4*)(og + h2 * 32);
            #pragma unroll
            for (int c = 0; c < 4; c++)
                o4[c] = make_uint4(oh[4*c], oh[4*c+1], oh[4*c+2], oh[4*c+3]);
        }
    }
}

// ---------------------------------------------------------------------------
// Launch
// ---------------------------------------------------------------------------
extern "C" void kernel_launch(void* const* d_in, const int* in_sizes, int n_in,
                              void* d_out, int out_size)
{
    (void)in_sizes; (void)n_in; (void)out_size;
    const float* x    = (const float*)d_in[0];
    const float* Wq   = (const float*)d_in[1];
    const float* Wkv  = (const float*)d_in[2];
    const float* Wout = (const float*)d_in[3];
    const float* bout = (const float*)d_in[4];
    const float* pos  = (const float*)d_in[5];
    float* out = (float*)d_out;

    __half *xh, *wqh, *wkvh, *wouth, *qh, *kvh, *ih;
    cudaGetSymbolAddress((void**)&xh,    g_xh);
    cudaGetSymbolAddress((void**)&wqh,   g_wqh);
    cudaGetSymbolAddress((void**)&wkvh,  g_wkvh);
    cudaGetSymbolAddress((void**)&wouth, g_wouth);
    cudaGetSymbolAddress((void**)&qh,    g_qh);
    cudaGetSymbolAddress((void**)&kvh,   g_kvh);
    cudaGetSymbolAddress((void**)&ih,    g_ih);

    cudaFuncSetAttribute(gemm_f16<true>,
        cudaFuncAttributeMaxDynamicSharedMemorySize, GEMM_SMEM);
    cudaFuncSetAttribute(gemm_f16<false>,
        cudaFuncAttributeMaxDynamicSharedMemorySize, GEMM_SMEM);
    cudaFuncSetAttribute(attn_f16,
        cudaFuncAttributeMaxDynamicSharedMemorySize, ATTN_SMEM);

    // 0) fp32 -> fp16 conversions
    int nx = NROWS * DIM;
    f2h_kernel<<<nx / 4 / 256, 256>>>(x, xh, nx);
    f2h_kernel<<<(DIM * INNER) / 4 / 256, 256>>>(Wq, wqh, DIM * INNER);
    f2h_kernel<<<(DIM * 2 * INNER) / 4 / 256, 256>>>(Wkv, wkvh, DIM * 2 * INNER);
    f2h_kernel<<<(INNER * DIM) / 4 / 256, 256>>>(Wout, wouth, INNER * DIM);

    // 1) q = x @ Wq   (fp16 out)
    gemm_f16<true><<<dim3(INNER / GBN, NROWS / GBM), 256, GEMM_SMEM>>>(
        xh, wqh, nullptr, qh, NROWS, INNER, DIM);
    // 2) kv = x @ Wkv (fp16 out)
    gemm_f16<true><<<dim3(2 * INNER / GBN, NROWS / GBM), 256, GEMM_SMEM>>>(
        xh, wkvh, nullptr, kvh, NROWS, 2 * INNER, DIM);
    // 3) attention
    attn_f16<<<NBLK, 256, ATTN_SMEM>>>(qh, kvh, pos, ih);
    // 4) out = inner @ Wout + b (fp32 out)
    gemm_f16<false><<<dim3(DIM / GBN, NROWS / GBM), 256, GEMM_SMEM>>>(
        ih, wouth, bout, out, NROWS, DIM, INNER);
}